// round 11
// baseline (speedup 1.0000x reference)
#include <cuda_runtime.h>
#include <cuda_bf16.h>
#include <cstdint>

// ---------------------------------------------------------------------------
// HeteroEdgePromptPlus — folded formulation.
//   logits[e,k] = srcLogits[src(e),k] + dstLogits[dst(e),k]   (bias folded)
//   b = softmax(leaky_relu(logits)) ; out[e] = b @ A
// Fused edge kernel: 3-stage SW pipeline + TMA bulk-store epilogue (stores
// leave via cp.async.bulk from smem staging; no STG/L1tex on the hot path).
// ---------------------------------------------------------------------------

#define MAXN 50000
typedef unsigned long long ull;

// fold outputs in ONE buffer (single memset): Mp | Ma | cp | ca
__device__ float g_fold[48 * 256 + 16 * 128 + 48 + 16];
#define G_MP (g_fold)
#define G_MA (g_fold + 12288)
#define G_CP (g_fold + 14336)
#define G_CA (g_fold + 14384)
__device__ float g_paperL[(size_t)MAXN * 48];
__device__ float g_authorL[(size_t)MAXN * 16];

// ---- f32x2 packed helpers (Blackwell) -------------------------------------
__device__ __forceinline__ ull pk2(float x, float y) {
    ull r;
    asm("mov.b64 %0, {%1, %2};" : "=l"(r) : "f"(x), "f"(y));
    return r;
}
__device__ __forceinline__ void upk(ull v, float& x, float& y) {
    asm("mov.b64 {%0, %1}, %2;" : "=f"(x), "=f"(y) : "l"(v));
}
__device__ __forceinline__ void fma2(ull& d, ull a, ull b) {
    asm("fma.rn.f32x2 %0, %1, %2, %0;" : "+l"(d) : "l"(a), "l"(b));
}
__device__ __forceinline__ void st4cs(float* p, ull a, ull b) {
    float x, y, z, w;
    upk(a, x, y);
    upk(b, z, w);
    asm volatile("st.global.cs.v4.f32 [%0], {%1, %2, %3, %4};"
                 :: "l"(p), "f"(x), "f"(y), "f"(z), "f"(w) : "memory");
}
__device__ __forceinline__ void st4s(float4* p, ull a, ull b) {
    float x, y, z, w;
    upk(a, x, y);
    upk(b, z, w);
    *p = make_float4(x, y, z, w);
}

// ---- TMA bulk 1D store helpers ---------------------------------------------
__device__ __forceinline__ uint32_t smem_u32(const void* p) {
    uint32_t a;
    asm("{ .reg .u64 t; cvta.to.shared.u64 t, %1; cvt.u32.u64 %0, t; }"
        : "=r"(a) : "l"(p));
    return a;
}
__device__ __forceinline__ void tma_store_1d(float* gdst, uint32_t ssrc,
                                             int bytes) {
    asm volatile("cp.async.bulk.global.shared::cta.bulk_group [%0], [%1], %2;"
                 :: "l"(gdst), "r"(ssrc), "r"(bytes) : "memory");
}
#define TMA_COMMIT() \
    asm volatile("cp.async.bulk.commit_group;" ::: "memory")
#define TMA_WAIT_READ1() \
    asm volatile("cp.async.bulk.wait_group.read 1;" ::: "memory")
#define TMA_WAIT_ALL() \
    asm volatile("cp.async.bulk.wait_group 0;" ::: "memory")
#define FENCE_ASYNC() \
    asm volatile("fence.proxy.async.shared::cta;" ::: "memory")

// ---------------------------------------------------------------------------
// Kernel 1: fold weights. grid = (64, 4): x = output row, y = p-chunk of 32.
// ---------------------------------------------------------------------------
__global__ void fold_kernel(const float* __restrict__ Wp_p,
                            const float* __restrict__ bp_p,
                            const float* __restrict__ Wp_a,
                            const float* __restrict__ bp_a,
                            const float* __restrict__ Ws_w,
                            const float* __restrict__ bs_w,
                            const float* __restrict__ Ws_c,
                            const float* __restrict__ bs_c) {
    const int b = blockIdx.x, t = threadIdx.x;
    const int pBeg = blockIdx.y * 32, pEnd = pBeg + 32;
    if (b < 48) {
        int k = b & 15, grp = b >> 4;
        const float* wrow = (grp == 0) ? (Ws_w + k * 256 + 128)
                          : (grp == 1) ? (Ws_c + k * 256)
                                       : (Ws_c + k * 256 + 128);
        float a0 = 0.f, a1 = 0.f, a2 = 0.f, a3 = 0.f;
        #pragma unroll
        for (int p = pBeg; p < pEnd; p += 4) {
            a0 = fmaf(__ldg(&wrow[p + 0]), __ldg(&Wp_p[(p + 0) * 256 + t]), a0);
            a1 = fmaf(__ldg(&wrow[p + 1]), __ldg(&Wp_p[(p + 1) * 256 + t]), a1);
            a2 = fmaf(__ldg(&wrow[p + 2]), __ldg(&Wp_p[(p + 2) * 256 + t]), a2);
            a3 = fmaf(__ldg(&wrow[p + 3]), __ldg(&Wp_p[(p + 3) * 256 + t]), a3);
        }
        atomicAdd(&G_MP[b * 256 + t], (a0 + a1) + (a2 + a3));
        if (t == 0) {
            float c0 = (blockIdx.y == 0)
                           ? ((grp == 0) ? bs_w[k] : (grp == 2) ? bs_c[k] : 0.f)
                           : 0.f;
            float c1 = 0.f, c2 = 0.f, c3 = 0.f;
            #pragma unroll
            for (int p = pBeg; p < pEnd; p += 4) {
                c0 = fmaf(wrow[p + 0], bp_p[p + 0], c0);
                c1 = fmaf(wrow[p + 1], bp_p[p + 1], c1);
                c2 = fmaf(wrow[p + 2], bp_p[p + 2], c2);
                c3 = fmaf(wrow[p + 3], bp_p[p + 3], c3);
            }
            atomicAdd(&G_CP[b], (c0 + c1) + (c2 + c3));
        }
    } else {
        int k = b - 48;
        if (t < 128) {
            const float* wrow = Ws_w + k * 256;  // src half -> author
            float a0 = 0.f, a1 = 0.f, a2 = 0.f, a3 = 0.f;
            #pragma unroll
            for (int p = pBeg; p < pEnd; p += 4) {
                a0 = fmaf(__ldg(&wrow[p + 0]), __ldg(&Wp_a[(p + 0) * 128 + t]), a0);
                a1 = fmaf(__ldg(&wrow[p + 1]), __ldg(&Wp_a[(p + 1) * 128 + t]), a1);
                a2 = fmaf(__ldg(&wrow[p + 2]), __ldg(&Wp_a[(p + 2) * 128 + t]), a2);
                a3 = fmaf(__ldg(&wrow[p + 3]), __ldg(&Wp_a[(p + 3) * 128 + t]), a3);
            }
            atomicAdd(&G_MA[k * 128 + t], (a0 + a1) + (a2 + a3));
            if (t == 0) {
                float c0 = 0.f, c1 = 0.f, c2 = 0.f, c3 = 0.f;
                #pragma unroll
                for (int p = pBeg; p < pEnd; p += 4) {
                    c0 = fmaf(wrow[p + 0], bp_a[p + 0], c0);
                    c1 = fmaf(wrow[p + 1], bp_a[p + 1], c1);
                    c2 = fmaf(wrow[p + 2], bp_a[p + 2], c2);
                    c3 = fmaf(wrow[p + 3], bp_a[p + 3], c3);
                }
                atomicAdd(&G_CA[k], (c0 + c1) + (c2 + c3));
            }
        }
    }
}

// ---------------------------------------------------------------------------
// Kernel 2: node logits  out[N,KOUT] = X[N,KDIM] @ M[KOUT,KDIM].T + c
// ---------------------------------------------------------------------------
template <int KDIM, int KOUT, int OPT>
__device__ __forceinline__ void node_body(const float* __restrict__ X,
                                          const float* __restrict__ M,
                                          const float* __restrict__ c,
                                          float* __restrict__ out, int N,
                                          int blk, float* Xs, float* Ms) {
    constexpr int KT = 32;
    const int t = threadIdx.x;
    const int n0 = blk * 128;
    const int ng = t & 63;
    const int og = t >> 6;

    ull acc0[OPT / 2], acc1[OPT / 2];
    #pragma unroll
    for (int i = 0; i < OPT / 2; i++) { acc0[i] = 0ull; acc1[i] = 0ull; }

    const int sn = n0 + (t >> 1);
    const int sj = (t & 1) * 16;
    const bool vs = sn < N;
    const float* xrow = X + (size_t)(vs ? sn : (N - 1)) * KDIM;

    for (int j0 = 0; j0 < KDIM; j0 += KT) {
        #pragma unroll
        for (int q = 0; q < 4; q++) {
            float4 v = vs ? *reinterpret_cast<const float4*>(xrow + j0 + sj + 4 * q)
                          : make_float4(0.f, 0.f, 0.f, 0.f);
            int jj = sj + 4 * q;
            Xs[(jj + 0) * 128 + (t >> 1)] = v.x;
            Xs[(jj + 1) * 128 + (t >> 1)] = v.y;
            Xs[(jj + 2) * 128 + (t >> 1)] = v.z;
            Xs[(jj + 3) * 128 + (t >> 1)] = v.w;
        }
        #pragma unroll
        for (int idx = t; idx < KT * KOUT; idx += 256) {
            int j = idx / KOUT, k = idx - j * KOUT;
            Ms[j * KOUT + k] = M[k * KDIM + j0 + j];
        }
        __syncthreads();
        #pragma unroll
        for (int j = 0; j < KT; j++) {
            float2 xv = *reinterpret_cast<const float2*>(&Xs[j * 128 + 2 * ng]);
            ull xx = pk2(xv.x, xv.x);
            ull yy = pk2(xv.y, xv.y);
            #pragma unroll
            for (int cp = 0; cp < OPT / 2; cp++) {
                ull m2 = *reinterpret_cast<const ull*>(&Ms[j * KOUT + og * OPT + 2 * cp]);
                fma2(acc0[cp], xx, m2);
                fma2(acc1[cp], yy, m2);
            }
        }
        __syncthreads();
    }

    float r0[OPT], r1[OPT];
    #pragma unroll
    for (int cp = 0; cp < OPT / 2; cp++) {
        upk(acc0[cp], r0[2 * cp], r0[2 * cp + 1]);
        upk(acc1[cp], r1[2 * cp], r1[2 * cp + 1]);
    }
    #pragma unroll
    for (int cc = 0; cc < OPT; cc++) {
        float bias = __ldg(&c[og * OPT + cc]);
        r0[cc] += bias;
        r1[cc] += bias;
    }
    const int nA = n0 + 2 * ng, nB = nA + 1;
    if (nA < N) {
        #pragma unroll
        for (int v = 0; v < OPT / 4; v++)
            *reinterpret_cast<float4*>(&out[(size_t)nA * KOUT + og * OPT + 4 * v]) =
                make_float4(r0[4 * v], r0[4 * v + 1], r0[4 * v + 2], r0[4 * v + 3]);
    }
    if (nB < N) {
        #pragma unroll
        for (int v = 0; v < OPT / 4; v++)
            *reinterpret_cast<float4*>(&out[(size_t)nB * KOUT + og * OPT + 4 * v]) =
                make_float4(r1[4 * v], r1[4 * v + 1], r1[4 * v + 2], r1[4 * v + 3]);
    }
}

__global__ void __launch_bounds__(256)
node_kernel(const float* __restrict__ xp, const float* __restrict__ xa,
            const float* __restrict__ Mp, const float* __restrict__ cp,
            const float* __restrict__ Ma, const float* __restrict__ ca,
            float* __restrict__ pL, float* __restrict__ aL,
            int Np, int Na, int npBlocks) {
    __shared__ float Xs[32 * 128];
    __shared__ float Ms[32 * 48];
    if ((int)blockIdx.x < npBlocks)
        node_body<256, 48, 12>(xp, Mp, cp, pL, Np, blockIdx.x, Xs, Ms);
    else
        node_body<128, 16, 4>(xa, Ma, ca, aL, Na, blockIdx.x - npBlocks, Xs, Ms);
}

// ---------------------------------------------------------------------------
// Kernel 3 (fused, merged edge types): A in regs (4 cols/lane), broadcast
// LDS, (256,2). 3-stage pipeline per iteration:
//   softmax(batch t+1) -> bsh[buf^1]
//   issue gathers for batch t+2 -> lg
//   epilogue FMA batch t -> smem staging -> TMA bulk store (4KB contiguous)
// Double-buffered staging recycled via cp.async.bulk.wait_group.read.
// ---------------------------------------------------------------------------
__global__ void __launch_bounds__(256, 2)
edge_fused_kernel(const int* __restrict__ eiW, const int* __restrict__ eiC,
                  int E,
                  const float* __restrict__ aL, const float* __restrict__ pL,
                  const float* __restrict__ A_w, const float* __restrict__ A_c,
                  float* __restrict__ out, int nbHalf) {
    __shared__ __align__(16) float2 bsh[8][2][4][32];   // [warp][buf][pair][{b,b}x16]
    __shared__ __align__(16) float4 osb[8][2][8][32];   // [warp][buf][edge][lane] 64KB

    const bool isW = (int)blockIdx.x < nbHalf;
    const int bid = isW ? blockIdx.x : blockIdx.x - nbHalf;
    const int* ei = isW ? eiW : eiC;
    const float* srcL = isW ? aL : (pL + 16);
    const int sStride = isW ? 16 : 48;
    const float* dstL = isW ? pL : (pL + 32);
    const float* A = isW ? A_w : A_c;
    float* o = isW ? out : out + (size_t)E * 128;

    const int lane = threadIdx.x & 31;
    const int w = threadIdx.x >> 5;
    const int k16 = lane & 15;
    const int half = lane >> 4;

    // A preload: lane owns output columns [4*lane, 4*lane+4) for all 16 k.
    ull aLr[16], aHr[16];
    #pragma unroll
    for (int k = 0; k < 16; k++) {
        float4 v = reinterpret_cast<const float4*>(A)[k * 32 + lane];
        aLr[k] = pk2(v.x, v.y);
        aHr[k] = pk2(v.z, v.w);
    }

    const uint32_t osbAddr[2] = { smem_u32(&osb[w][0][0][0]),
                                  smem_u32(&osb[w][1][0][0]) };

    const int pairs = E >> 1;              // E even
    const int gw = bid * 8 + w;
    const int base = gw * 4;
    const int step = nbHalf * 8 * 4;       // pairs consumed per iter, all warps
    if (base >= pairs) return;
    const int nIter = (pairs - base + step - 1) / step;

    float lg[4];

    // gather + leaky-relu logits for batch t (clamped; safe for any t)
    #define GATHER(t_)                                                        \
        do {                                                                  \
            int pb_ = base + (t_) * step;                                     \
            _Pragma("unroll")                                                 \
            for (int u = 0; u < 4; u++) {                                     \
                int e_ = min(2 * (pb_ + u) + half, E - 1);                    \
                int s_ = __ldg(&ei[e_]);                                      \
                int d_ = __ldg(&ei[E + e_]);                                  \
                float l_ = __ldg(&srcL[(size_t)s_ * sStride + k16]) +         \
                           __ldg(&dstL[(size_t)d_ * 48 + k16]);               \
                lg[u] = fmaxf(l_, 0.01f * l_);                                \
            }                                                                 \
        } while (0)

    // no-max softmax (logits bounded; fp32 headroom is huge) -> bsh[w][buf_]
    #define SOFTMAX_TO(buf_)                                                  \
        do {                                                                  \
            float ex_[4], sm_[4];                                             \
            _Pragma("unroll")                                                 \
            for (int u = 0; u < 4; u++) {                                     \
                ex_[u] = __expf(lg[u]);                                       \
                sm_[u] = ex_[u];                                              \
            }                                                                 \
            _Pragma("unroll")                                                 \
            for (int m = 8; m; m >>= 1) {                                     \
                _Pragma("unroll")                                             \
                for (int u = 0; u < 4; u++)                                   \
                    sm_[u] += __shfl_xor_sync(0xffffffffu, sm_[u], m, 16);    \
            }                                                                 \
            _Pragma("unroll")                                                 \
            for (int u = 0; u < 4; u++) {                                     \
                float b_ = __fdividef(ex_[u], sm_[u]);                        \
                bsh[w][buf_][u][lane] = make_float2(b_, b_);                  \
            }                                                                 \
        } while (0)

    // prologue: batch 0 softmax into buf 0; issue batch-1 gathers
    GATHER(0);
    SOFTMAX_TO(0);
    GATHER(1);
    __syncwarp();

    for (int t = 0; t < nIter; t++) {
        const int buf = t & 1;

        // stage 1: softmax batch t+1 (gathers issued last iter) -> buf^1
        SOFTMAX_TO(buf ^ 1);
        // stage 2: issue gathers batch t+2 (fly under the FMA burst)
        GATHER(t + 2);

        // recycle staging buffer: TMA reads of osb[buf] (iter t-2) must be done
        if (t >= 2 && lane == 0) TMA_WAIT_READ1();
        __syncwarp();

        // stage 3: epilogue batch t from bsh[buf]
        const int pb = base + t * step;
        const bool full = (pb + 4 <= pairs);
        if (full) {
            #pragma unroll
            for (int u = 0; u < 4; u++) {
                #pragma unroll
                for (int h = 0; h < 2; h++) {
                    const ulonglong2* bq =
                        reinterpret_cast<const ulonglong2*>(&bsh[w][buf][u][16 * h]);
                    ull accL = 0ull, accH = 0ull;
                    #pragma unroll
                    for (int k2 = 0; k2 < 8; k2++) {
                        ulonglong2 q = bq[k2];
                        fma2(accL, q.x, aLr[2 * k2]);
                        fma2(accH, q.x, aHr[2 * k2]);
                        fma2(accL, q.y, aLr[2 * k2 + 1]);
                        fma2(accH, q.y, aHr[2 * k2 + 1]);
                    }
                    st4s(&osb[w][buf][2 * u + h][lane], accL, accH);
                }
            }
            __syncwarp();
            if (lane == 0) {
                FENCE_ASYNC();
                tma_store_1d(o + (size_t)(2 * pb) * 128, osbAddr[buf], 4096);
                TMA_COMMIT();
            }
        } else {
            // tail: direct streaming stores
            #pragma unroll
            for (int u = 0; u < 4; u++) {
                if (pb + u < pairs) {
                    #pragma unroll
                    for (int h = 0; h < 2; h++) {
                        const ulonglong2* bq =
                            reinterpret_cast<const ulonglong2*>(&bsh[w][buf][u][16 * h]);
                        ull accL = 0ull, accH = 0ull;
                        #pragma unroll
                        for (int k2 = 0; k2 < 8; k2++) {
                            ulonglong2 q = bq[k2];
                            fma2(accL, q.x, aLr[2 * k2]);
                            fma2(accH, q.x, aHr[2 * k2]);
                            fma2(accL, q.y, aLr[2 * k2 + 1]);
                            fma2(accH, q.y, aHr[2 * k2 + 1]);
                        }
                        st4cs(o + (size_t)(2 * (pb + u) + h) * 128 + 4 * lane,
                              accL, accH);
                    }
                }
            }
        }
        __syncwarp();
    }
    // flush outstanding bulk stores before exit
    if (lane == 0) TMA_WAIT_ALL();
    #undef GATHER
    #undef SOFTMAX_TO
}

// ---------------------------------------------------------------------------
extern "C" void kernel_launch(void* const* d_in, const int* in_sizes, int n_in,
                              void* d_out, int out_size) {
    const float* x_paper   = (const float*)d_in[0];
    const float* x_author  = (const float*)d_in[1];
    const float* Wp_paper  = (const float*)d_in[2];
    const float* bp_paper  = (const float*)d_in[3];
    const float* Wp_author = (const float*)d_in[4];
    const float* bp_author = (const float*)d_in[5];
    const float* Ws_writes = (const float*)d_in[6];
    const float* bs_writes = (const float*)d_in[7];
    const float* A_writes  = (const float*)d_in[8];
    const float* Ws_cites  = (const float*)d_in[9];
    const float* bs_cites  = (const float*)d_in[10];
    const float* A_cites   = (const float*)d_in[11];
    const int*   ei_writes = (const int*)d_in[12];
    const int*   ei_cites  = (const int*)d_in[13];
    float* out = (float*)d_out;

    const int Np = in_sizes[0] / 256;
    const int Na = in_sizes[1] / 128;
    const int E  = in_sizes[12] / 2;

    float *fold, *pL, *aL;
    cudaGetSymbolAddress((void**)&fold, g_fold);
    cudaGetSymbolAddress((void**)&pL, g_paperL);
    cudaGetSymbolAddress((void**)&aL, g_authorL);
    float* Mp = fold;
    float* Ma = fold + 12288;
    float* cp = fold + 14336;
    float* ca = fold + 14384;

    cudaMemsetAsync(fold, 0, 14400 * sizeof(float));

    fold_kernel<<<dim3(64, 4), 256>>>(Wp_paper, bp_paper, Wp_author, bp_author,
                                      Ws_writes, bs_writes, Ws_cites, bs_cites);

    const int npB = (Np + 127) / 128;
    const int naB = (Na + 127) / 128;
    node_kernel<<<npB + naB, 256>>>(x_paper, x_author, Mp, cp, Ma, ca,
                                    pL, aL, Np, Na, npB);

    const int nbHalf = 148;  // persistent single wave: 2 CTAs/SM
    edge_fused_kernel<<<2 * nbHalf, 256>>>(ei_writes, ei_cites, E, aL, pL,
                                           A_writes, A_cites, out, nbHalf);
}

// round 12
// speedup vs baseline: 1.1106x; 1.1106x over previous
#include <cuda_runtime.h>
#include <cuda_bf16.h>
#include <cstdint>

// ---------------------------------------------------------------------------
// HeteroEdgePromptPlus — folded formulation.
//   logits[e,k] = srcLogits[src(e),k] + dstLogits[dst(e),k]   (bias folded)
//   b = softmax(leaky_relu(logits)) ; out[e] = b @ A
// Fused edge kernel: 3-stage SW pipeline; b stored UNduplicated in smem
// (4 broadcast LDS.128/edge + reg-side {b,b} packing) to cut L1tex wavefronts.
// ---------------------------------------------------------------------------

#define MAXN 50000
typedef unsigned long long ull;

// fold outputs in ONE buffer (single memset): Mp | Ma | cp | ca
__device__ float g_fold[48 * 256 + 16 * 128 + 48 + 16];
#define G_MP (g_fold)
#define G_MA (g_fold + 12288)
#define G_CP (g_fold + 14336)
#define G_CA (g_fold + 14384)
__device__ float g_paperL[(size_t)MAXN * 48];
__device__ float g_authorL[(size_t)MAXN * 16];

// ---- f32x2 packed helpers (Blackwell) -------------------------------------
__device__ __forceinline__ ull pk2(float x, float y) {
    ull r;
    asm("mov.b64 %0, {%1, %2};" : "=l"(r) : "f"(x), "f"(y));
    return r;
}
__device__ __forceinline__ void upk(ull v, float& x, float& y) {
    asm("mov.b64 {%0, %1}, %2;" : "=f"(x), "=f"(y) : "l"(v));
}
__device__ __forceinline__ void fma2(ull& d, ull a, ull b) {
    asm("fma.rn.f32x2 %0, %1, %2, %0;" : "+l"(d) : "l"(a), "l"(b));
}
__device__ __forceinline__ void st4cs(float* p, ull a, ull b) {
    float x, y, z, w;
    upk(a, x, y);
    upk(b, z, w);
    asm volatile("st.global.cs.v4.f32 [%0], {%1, %2, %3, %4};"
                 :: "l"(p), "f"(x), "f"(y), "f"(z), "f"(w) : "memory");
}

// ---------------------------------------------------------------------------
// Kernel 1: fold weights. grid = (64, 4): x = output row, y = p-chunk of 32.
// ---------------------------------------------------------------------------
__global__ void fold_kernel(const float* __restrict__ Wp_p,
                            const float* __restrict__ bp_p,
                            const float* __restrict__ Wp_a,
                            const float* __restrict__ bp_a,
                            const float* __restrict__ Ws_w,
                            const float* __restrict__ bs_w,
                            const float* __restrict__ Ws_c,
                            const float* __restrict__ bs_c) {
    const int b = blockIdx.x, t = threadIdx.x;
    const int pBeg = blockIdx.y * 32, pEnd = pBeg + 32;
    if (b < 48) {
        int k = b & 15, grp = b >> 4;
        const float* wrow = (grp == 0) ? (Ws_w + k * 256 + 128)
                          : (grp == 1) ? (Ws_c + k * 256)
                                       : (Ws_c + k * 256 + 128);
        float a0 = 0.f, a1 = 0.f, a2 = 0.f, a3 = 0.f;
        #pragma unroll
        for (int p = pBeg; p < pEnd; p += 4) {
            a0 = fmaf(__ldg(&wrow[p + 0]), __ldg(&Wp_p[(p + 0) * 256 + t]), a0);
            a1 = fmaf(__ldg(&wrow[p + 1]), __ldg(&Wp_p[(p + 1) * 256 + t]), a1);
            a2 = fmaf(__ldg(&wrow[p + 2]), __ldg(&Wp_p[(p + 2) * 256 + t]), a2);
            a3 = fmaf(__ldg(&wrow[p + 3]), __ldg(&Wp_p[(p + 3) * 256 + t]), a3);
        }
        atomicAdd(&G_MP[b * 256 + t], (a0 + a1) + (a2 + a3));
        if (t == 0) {
            float c0 = (blockIdx.y == 0)
                           ? ((grp == 0) ? bs_w[k] : (grp == 2) ? bs_c[k] : 0.f)
                           : 0.f;
            float c1 = 0.f, c2 = 0.f, c3 = 0.f;
            #pragma unroll
            for (int p = pBeg; p < pEnd; p += 4) {
                c0 = fmaf(wrow[p + 0], bp_p[p + 0], c0);
                c1 = fmaf(wrow[p + 1], bp_p[p + 1], c1);
                c2 = fmaf(wrow[p + 2], bp_p[p + 2], c2);
                c3 = fmaf(wrow[p + 3], bp_p[p + 3], c3);
            }
            atomicAdd(&G_CP[b], (c0 + c1) + (c2 + c3));
        }
    } else {
        int k = b - 48;
        if (t < 128) {
            const float* wrow = Ws_w + k * 256;  // src half -> author
            float a0 = 0.f, a1 = 0.f, a2 = 0.f, a3 = 0.f;
            #pragma unroll
            for (int p = pBeg; p < pEnd; p += 4) {
                a0 = fmaf(__ldg(&wrow[p + 0]), __ldg(&Wp_a[(p + 0) * 128 + t]), a0);
                a1 = fmaf(__ldg(&wrow[p + 1]), __ldg(&Wp_a[(p + 1) * 128 + t]), a1);
                a2 = fmaf(__ldg(&wrow[p + 2]), __ldg(&Wp_a[(p + 2) * 128 + t]), a2);
                a3 = fmaf(__ldg(&wrow[p + 3]), __ldg(&Wp_a[(p + 3) * 128 + t]), a3);
            }
            atomicAdd(&G_MA[k * 128 + t], (a0 + a1) + (a2 + a3));
            if (t == 0) {
                float c0 = 0.f, c1 = 0.f, c2 = 0.f, c3 = 0.f;
                #pragma unroll
                for (int p = pBeg; p < pEnd; p += 4) {
                    c0 = fmaf(wrow[p + 0], bp_a[p + 0], c0);
                    c1 = fmaf(wrow[p + 1], bp_a[p + 1], c1);
                    c2 = fmaf(wrow[p + 2], bp_a[p + 2], c2);
                    c3 = fmaf(wrow[p + 3], bp_a[p + 3], c3);
                }
                atomicAdd(&G_CA[k], (c0 + c1) + (c2 + c3));
            }
        }
    }
}

// ---------------------------------------------------------------------------
// Kernel 2: node logits  out[N,KOUT] = X[N,KDIM] @ M[KOUT,KDIM].T + c
// ---------------------------------------------------------------------------
template <int KDIM, int KOUT, int OPT>
__device__ __forceinline__ void node_body(const float* __restrict__ X,
                                          const float* __restrict__ M,
                                          const float* __restrict__ c,
                                          float* __restrict__ out, int N,
                                          int blk, float* Xs, float* Ms) {
    constexpr int KT = 32;
    const int t = threadIdx.x;
    const int n0 = blk * 128;
    const int ng = t & 63;
    const int og = t >> 6;

    ull acc0[OPT / 2], acc1[OPT / 2];
    #pragma unroll
    for (int i = 0; i < OPT / 2; i++) { acc0[i] = 0ull; acc1[i] = 0ull; }

    const int sn = n0 + (t >> 1);
    const int sj = (t & 1) * 16;
    const bool vs = sn < N;
    const float* xrow = X + (size_t)(vs ? sn : (N - 1)) * KDIM;

    for (int j0 = 0; j0 < KDIM; j0 += KT) {
        #pragma unroll
        for (int q = 0; q < 4; q++) {
            float4 v = vs ? *reinterpret_cast<const float4*>(xrow + j0 + sj + 4 * q)
                          : make_float4(0.f, 0.f, 0.f, 0.f);
            int jj = sj + 4 * q;
            Xs[(jj + 0) * 128 + (t >> 1)] = v.x;
            Xs[(jj + 1) * 128 + (t >> 1)] = v.y;
            Xs[(jj + 2) * 128 + (t >> 1)] = v.z;
            Xs[(jj + 3) * 128 + (t >> 1)] = v.w;
        }
        #pragma unroll
        for (int idx = t; idx < KT * KOUT; idx += 256) {
            int j = idx / KOUT, k = idx - j * KOUT;
            Ms[j * KOUT + k] = M[k * KDIM + j0 + j];
        }
        __syncthreads();
        #pragma unroll
        for (int j = 0; j < KT; j++) {
            float2 xv = *reinterpret_cast<const float2*>(&Xs[j * 128 + 2 * ng]);
            ull xx = pk2(xv.x, xv.x);
            ull yy = pk2(xv.y, xv.y);
            #pragma unroll
            for (int cp = 0; cp < OPT / 2; cp++) {
                ull m2 = *reinterpret_cast<const ull*>(&Ms[j * KOUT + og * OPT + 2 * cp]);
                fma2(acc0[cp], xx, m2);
                fma2(acc1[cp], yy, m2);
            }
        }
        __syncthreads();
    }

    float r0[OPT], r1[OPT];
    #pragma unroll
    for (int cp = 0; cp < OPT / 2; cp++) {
        upk(acc0[cp], r0[2 * cp], r0[2 * cp + 1]);
        upk(acc1[cp], r1[2 * cp], r1[2 * cp + 1]);
    }
    #pragma unroll
    for (int cc = 0; cc < OPT; cc++) {
        float bias = __ldg(&c[og * OPT + cc]);
        r0[cc] += bias;
        r1[cc] += bias;
    }
    const int nA = n0 + 2 * ng, nB = nA + 1;
    if (nA < N) {
        #pragma unroll
        for (int v = 0; v < OPT / 4; v++)
            *reinterpret_cast<float4*>(&out[(size_t)nA * KOUT + og * OPT + 4 * v]) =
                make_float4(r0[4 * v], r0[4 * v + 1], r0[4 * v + 2], r0[4 * v + 3]);
    }
    if (nB < N) {
        #pragma unroll
        for (int v = 0; v < OPT / 4; v++)
            *reinterpret_cast<float4*>(&out[(size_t)nB * KOUT + og * OPT + 4 * v]) =
                make_float4(r1[4 * v], r1[4 * v + 1], r1[4 * v + 2], r1[4 * v + 3]);
    }
}

__global__ void __launch_bounds__(256)
node_kernel(const float* __restrict__ xp, const float* __restrict__ xa,
            const float* __restrict__ Mp, const float* __restrict__ cp,
            const float* __restrict__ Ma, const float* __restrict__ ca,
            float* __restrict__ pL, float* __restrict__ aL,
            int Np, int Na, int npBlocks) {
    __shared__ float Xs[32 * 128];
    __shared__ float Ms[32 * 48];
    if ((int)blockIdx.x < npBlocks)
        node_body<256, 48, 12>(xp, Mp, cp, pL, Np, blockIdx.x, Xs, Ms);
    else
        node_body<128, 16, 4>(xa, Ma, ca, aL, Na, blockIdx.x - npBlocks, Xs, Ms);
}

// ---------------------------------------------------------------------------
// Kernel 3 (fused, merged edge types): A in regs (4 cols/lane), (256,2),
// persistent grid. 3-stage pipeline per iteration:
//   softmax(batch t+1) -> bsh[buf^1]  (UNduplicated float; 1 STS wf/pair)
//   issue gathers for batch t+2 -> lg
//   epilogue batch t: per edge 4 broadcast LDS.128 + 16 {b,b} packs + 32 fma2
//                     + STG.128 streaming
// ---------------------------------------------------------------------------
__global__ void __launch_bounds__(256, 2)
edge_fused_kernel(const int* __restrict__ eiW, const int* __restrict__ eiC,
                  int E,
                  const float* __restrict__ aL, const float* __restrict__ pL,
                  const float* __restrict__ A_w, const float* __restrict__ A_c,
                  float* __restrict__ out, int nbHalf) {
    __shared__ __align__(16) float bsh[8][2][4][32];  // [warp][buf][pair][2e x 16k]

    const bool isW = (int)blockIdx.x < nbHalf;
    const int bid = isW ? blockIdx.x : blockIdx.x - nbHalf;
    const int* ei = isW ? eiW : eiC;
    const float* srcL = isW ? aL : (pL + 16);
    const int sStride = isW ? 16 : 48;
    const float* dstL = isW ? pL : (pL + 32);
    const float* A = isW ? A_w : A_c;
    float* o = isW ? out : out + (size_t)E * 128;

    const int lane = threadIdx.x & 31;
    const int w = threadIdx.x >> 5;
    const int k16 = lane & 15;
    const int half = lane >> 4;

    // A preload: lane owns output columns [4*lane, 4*lane+4) for all 16 k.
    ull aLr[16], aHr[16];
    #pragma unroll
    for (int k = 0; k < 16; k++) {
        float4 v = reinterpret_cast<const float4*>(A)[k * 32 + lane];
        aLr[k] = pk2(v.x, v.y);
        aHr[k] = pk2(v.z, v.w);
    }

    const int pairs = E >> 1;              // E even
    const int gw = bid * 8 + w;
    const int base = gw * 4;
    const int step = nbHalf * 8 * 4;       // pairs consumed per iter, all warps
    if (base >= pairs) return;
    const int nIter = (pairs - base + step - 1) / step;

    float lg[4];

    // gather + leaky-relu logits for batch t (clamped; safe for any t)
    #define GATHER(t_)                                                        \
        do {                                                                  \
            int pb_ = base + (t_) * step;                                     \
            _Pragma("unroll")                                                 \
            for (int u = 0; u < 4; u++) {                                     \
                int e_ = min(2 * (pb_ + u) + half, E - 1);                    \
                int s_ = __ldg(&ei[e_]);                                      \
                int d_ = __ldg(&ei[E + e_]);                                  \
                float l_ = __ldg(&srcL[(size_t)s_ * sStride + k16]) +         \
                           __ldg(&dstL[(size_t)d_ * 48 + k16]);               \
                lg[u] = fmaxf(l_, 0.01f * l_);                                \
            }                                                                 \
        } while (0)

    // no-max softmax (logits bounded; fp32 headroom is huge) -> bsh[w][buf_]
    #define SOFTMAX_TO(buf_)                                                  \
        do {                                                                  \
            float ex_[4], sm_[4];                                             \
            _Pragma("unroll")                                                 \
            for (int u = 0; u < 4; u++) {                                     \
                ex_[u] = __expf(lg[u]);                                       \
                sm_[u] = ex_[u];                                              \
            }                                                                 \
            _Pragma("unroll")                                                 \
            for (int m = 8; m; m >>= 1) {                                     \
                _Pragma("unroll")                                             \
                for (int u = 0; u < 4; u++)                                   \
                    sm_[u] += __shfl_xor_sync(0xffffffffu, sm_[u], m, 16);    \
            }                                                                 \
            _Pragma("unroll")                                                 \
            for (int u = 0; u < 4; u++)                                       \
                bsh[w][buf_][u][lane] = __fdividef(ex_[u], sm_[u]);           \
        } while (0)

    // prologue: batch 0 softmax into buf 0; issue batch-1 gathers
    GATHER(0);
    SOFTMAX_TO(0);
    GATHER(1);
    __syncwarp();

    for (int t = 0; t < nIter; t++) {
        const int buf = t & 1;

        // stage 1: softmax batch t+1 (gathers issued last iter) -> buf^1
        SOFTMAX_TO(buf ^ 1);
        // stage 2: issue gathers batch t+2 (fly under the FMA burst)
        GATHER(t + 2);

        // stage 3: epilogue batch t from bsh[buf]
        const int pb = base + t * step;
        #pragma unroll
        for (int u = 0; u < 4; u++) {
            if (pb + u < pairs) {
                #pragma unroll
                for (int h = 0; h < 2; h++) {
                    const float4* brow = reinterpret_cast<const float4*>(
                        &bsh[w][buf][u][16 * h]);
                    ull accL = 0ull, accH = 0ull;
                    #pragma unroll
                    for (int q = 0; q < 4; q++) {
                        float4 bv = brow[q];     // broadcast LDS.128
                        ull b0 = pk2(bv.x, bv.x);
                        ull b1 = pk2(bv.y, bv.y);
                        ull b2 = pk2(bv.z, bv.z);
                        ull b3 = pk2(bv.w, bv.w);
                        fma2(accL, b0, aLr[4 * q + 0]);
                        fma2(accH, b0, aHr[4 * q + 0]);
                        fma2(accL, b1, aLr[4 * q + 1]);
                        fma2(accH, b1, aHr[4 * q + 1]);
                        fma2(accL, b2, aLr[4 * q + 2]);
                        fma2(accH, b2, aHr[4 * q + 2]);
                        fma2(accL, b3, aLr[4 * q + 3]);
                        fma2(accH, b3, aHr[4 * q + 3]);
                    }
                    st4cs(o + (size_t)(2 * (pb + u) + h) * 128 + 4 * lane,
                          accL, accH);
                }
            }
        }
        __syncwarp();
    }
    #undef GATHER
    #undef SOFTMAX_TO
}

// ---------------------------------------------------------------------------
extern "C" void kernel_launch(void* const* d_in, const int* in_sizes, int n_in,
                              void* d_out, int out_size) {
    const float* x_paper   = (const float*)d_in[0];
    const float* x_author  = (const float*)d_in[1];
    const float* Wp_paper  = (const float*)d_in[2];
    const float* bp_paper  = (const float*)d_in[3];
    const float* Wp_author = (const float*)d_in[4];
    const float* bp_author = (const float*)d_in[5];
    const float* Ws_writes = (const float*)d_in[6];
    const float* bs_writes = (const float*)d_in[7];
    const float* A_writes  = (const float*)d_in[8];
    const float* Ws_cites  = (const float*)d_in[9];
    const float* bs_cites  = (const float*)d_in[10];
    const float* A_cites   = (const float*)d_in[11];
    const int*   ei_writes = (const int*)d_in[12];
    const int*   ei_cites  = (const int*)d_in[13];
    float* out = (float*)d_out;

    const int Np = in_sizes[0] / 256;
    const int Na = in_sizes[1] / 128;
    const int E  = in_sizes[12] / 2;

    float *fold, *pL, *aL;
    cudaGetSymbolAddress((void**)&fold, g_fold);
    cudaGetSymbolAddress((void**)&pL, g_paperL);
    cudaGetSymbolAddress((void**)&aL, g_authorL);
    float* Mp = fold;
    float* Ma = fold + 12288;
    float* cp = fold + 14336;
    float* ca = fold + 14384;

    cudaMemsetAsync(fold, 0, 14400 * sizeof(float));

    fold_kernel<<<dim3(64, 4), 256>>>(Wp_paper, bp_paper, Wp_author, bp_author,
                                      Ws_writes, bs_writes, Ws_cites, bs_cites);

    const int npB = (Np + 127) / 128;
    const int naB = (Na + 127) / 128;
    node_kernel<<<npB + naB, 256>>>(x_paper, x_author, Mp, cp, Ma, ca,
                                    pL, aL, Np, Na, npB);

    const int nbHalf = 148;  // persistent single wave: 2 CTAs/SM
    edge_fused_kernel<<<2 * nbHalf, 256>>>(ei_writes, ei_cites, E, aL, pL,
                                           A_writes, A_cites, out, nbHalf);
}

// round 13
// speedup vs baseline: 1.1611x; 1.0455x over previous
#include <cuda_runtime.h>
#include <cuda_bf16.h>
#include <cstdint>

// ---------------------------------------------------------------------------
// HeteroEdgePromptPlus — folded formulation.
//   logits[e,k] = srcLogits[src(e),k] + dstLogits[dst(e),k]   (bias folded)
//   b = softmax(leaky_relu(logits)) ; out[e] = b @ A
// Fused edge kernel: 3-stage SW pipeline; quad-per-edge float4 gathers
// (1 LDG.128 serves 8 edges), width-4 softmax reduction, unduplicated b in
// smem, A-in-regs consumer with broadcast LDS + streaming STG.128.
// ---------------------------------------------------------------------------

#define MAXN 50000
typedef unsigned long long ull;

// fold outputs in ONE buffer (single memset): Mp | Ma | cp | ca
__device__ float g_fold[48 * 256 + 16 * 128 + 48 + 16];
#define G_MP (g_fold)
#define G_MA (g_fold + 12288)
#define G_CP (g_fold + 14336)
#define G_CA (g_fold + 14384)
__device__ float g_paperL[(size_t)MAXN * 48];
__device__ float g_authorL[(size_t)MAXN * 16];

// ---- f32x2 packed helpers (Blackwell) -------------------------------------
__device__ __forceinline__ ull pk2(float x, float y) {
    ull r;
    asm("mov.b64 %0, {%1, %2};" : "=l"(r) : "f"(x), "f"(y));
    return r;
}
__device__ __forceinline__ void upk(ull v, float& x, float& y) {
    asm("mov.b64 {%0, %1}, %2;" : "=f"(x), "=f"(y) : "l"(v));
}
__device__ __forceinline__ void fma2(ull& d, ull a, ull b) {
    asm("fma.rn.f32x2 %0, %1, %2, %0;" : "+l"(d) : "l"(a), "l"(b));
}
__device__ __forceinline__ void st4cs(float* p, ull a, ull b) {
    float x, y, z, w;
    upk(a, x, y);
    upk(b, z, w);
    asm volatile("st.global.cs.v4.f32 [%0], {%1, %2, %3, %4};"
                 :: "l"(p), "f"(x), "f"(y), "f"(z), "f"(w) : "memory");
}

// ---------------------------------------------------------------------------
// Kernel 1: fold weights. grid = (64, 4): x = output row, y = p-chunk of 32.
// ---------------------------------------------------------------------------
__global__ void fold_kernel(const float* __restrict__ Wp_p,
                            const float* __restrict__ bp_p,
                            const float* __restrict__ Wp_a,
                            const float* __restrict__ bp_a,
                            const float* __restrict__ Ws_w,
                            const float* __restrict__ bs_w,
                            const float* __restrict__ Ws_c,
                            const float* __restrict__ bs_c) {
    const int b = blockIdx.x, t = threadIdx.x;
    const int pBeg = blockIdx.y * 32, pEnd = pBeg + 32;
    if (b < 48) {
        int k = b & 15, grp = b >> 4;
        const float* wrow = (grp == 0) ? (Ws_w + k * 256 + 128)
                          : (grp == 1) ? (Ws_c + k * 256)
                                       : (Ws_c + k * 256 + 128);
        float a0 = 0.f, a1 = 0.f, a2 = 0.f, a3 = 0.f;
        #pragma unroll
        for (int p = pBeg; p < pEnd; p += 4) {
            a0 = fmaf(__ldg(&wrow[p + 0]), __ldg(&Wp_p[(p + 0) * 256 + t]), a0);
            a1 = fmaf(__ldg(&wrow[p + 1]), __ldg(&Wp_p[(p + 1) * 256 + t]), a1);
            a2 = fmaf(__ldg(&wrow[p + 2]), __ldg(&Wp_p[(p + 2) * 256 + t]), a2);
            a3 = fmaf(__ldg(&wrow[p + 3]), __ldg(&Wp_p[(p + 3) * 256 + t]), a3);
        }
        atomicAdd(&G_MP[b * 256 + t], (a0 + a1) + (a2 + a3));
        if (t == 0) {
            float c0 = (blockIdx.y == 0)
                           ? ((grp == 0) ? bs_w[k] : (grp == 2) ? bs_c[k] : 0.f)
                           : 0.f;
            float c1 = 0.f, c2 = 0.f, c3 = 0.f;
            #pragma unroll
            for (int p = pBeg; p < pEnd; p += 4) {
                c0 = fmaf(wrow[p + 0], bp_p[p + 0], c0);
                c1 = fmaf(wrow[p + 1], bp_p[p + 1], c1);
                c2 = fmaf(wrow[p + 2], bp_p[p + 2], c2);
                c3 = fmaf(wrow[p + 3], bp_p[p + 3], c3);
            }
            atomicAdd(&G_CP[b], (c0 + c1) + (c2 + c3));
        }
    } else {
        int k = b - 48;
        if (t < 128) {
            const float* wrow = Ws_w + k * 256;  // src half -> author
            float a0 = 0.f, a1 = 0.f, a2 = 0.f, a3 = 0.f;
            #pragma unroll
            for (int p = pBeg; p < pEnd; p += 4) {
                a0 = fmaf(__ldg(&wrow[p + 0]), __ldg(&Wp_a[(p + 0) * 128 + t]), a0);
                a1 = fmaf(__ldg(&wrow[p + 1]), __ldg(&Wp_a[(p + 1) * 128 + t]), a1);
                a2 = fmaf(__ldg(&wrow[p + 2]), __ldg(&Wp_a[(p + 2) * 128 + t]), a2);
                a3 = fmaf(__ldg(&wrow[p + 3]), __ldg(&Wp_a[(p + 3) * 128 + t]), a3);
            }
            atomicAdd(&G_MA[k * 128 + t], (a0 + a1) + (a2 + a3));
            if (t == 0) {
                float c0 = 0.f, c1 = 0.f, c2 = 0.f, c3 = 0.f;
                #pragma unroll
                for (int p = pBeg; p < pEnd; p += 4) {
                    c0 = fmaf(wrow[p + 0], bp_a[p + 0], c0);
                    c1 = fmaf(wrow[p + 1], bp_a[p + 1], c1);
                    c2 = fmaf(wrow[p + 2], bp_a[p + 2], c2);
                    c3 = fmaf(wrow[p + 3], bp_a[p + 3], c3);
                }
                atomicAdd(&G_CA[k], (c0 + c1) + (c2 + c3));
            }
        }
    }
}

// ---------------------------------------------------------------------------
// Kernel 2: node logits  out[N,KOUT] = X[N,KDIM] @ M[KOUT,KDIM].T + c
// ---------------------------------------------------------------------------
template <int KDIM, int KOUT, int OPT>
__device__ __forceinline__ void node_body(const float* __restrict__ X,
                                          const float* __restrict__ M,
                                          const float* __restrict__ c,
                                          float* __restrict__ out, int N,
                                          int blk, float* Xs, float* Ms) {
    constexpr int KT = 32;
    const int t = threadIdx.x;
    const int n0 = blk * 128;
    const int ng = t & 63;
    const int og = t >> 6;

    ull acc0[OPT / 2], acc1[OPT / 2];
    #pragma unroll
    for (int i = 0; i < OPT / 2; i++) { acc0[i] = 0ull; acc1[i] = 0ull; }

    const int sn = n0 + (t >> 1);
    const int sj = (t & 1) * 16;
    const bool vs = sn < N;
    const float* xrow = X + (size_t)(vs ? sn : (N - 1)) * KDIM;

    for (int j0 = 0; j0 < KDIM; j0 += KT) {
        #pragma unroll
        for (int q = 0; q < 4; q++) {
            float4 v = vs ? *reinterpret_cast<const float4*>(xrow + j0 + sj + 4 * q)
                          : make_float4(0.f, 0.f, 0.f, 0.f);
            int jj = sj + 4 * q;
            Xs[(jj + 0) * 128 + (t >> 1)] = v.x;
            Xs[(jj + 1) * 128 + (t >> 1)] = v.y;
            Xs[(jj + 2) * 128 + (t >> 1)] = v.z;
            Xs[(jj + 3) * 128 + (t >> 1)] = v.w;
        }
        #pragma unroll
        for (int idx = t; idx < KT * KOUT; idx += 256) {
            int j = idx / KOUT, k = idx - j * KOUT;
            Ms[j * KOUT + k] = M[k * KDIM + j0 + j];
        }
        __syncthreads();
        #pragma unroll
        for (int j = 0; j < KT; j++) {
            float2 xv = *reinterpret_cast<const float2*>(&Xs[j * 128 + 2 * ng]);
            ull xx = pk2(xv.x, xv.x);
            ull yy = pk2(xv.y, xv.y);
            #pragma unroll
            for (int cp = 0; cp < OPT / 2; cp++) {
                ull m2 = *reinterpret_cast<const ull*>(&Ms[j * KOUT + og * OPT + 2 * cp]);
                fma2(acc0[cp], xx, m2);
                fma2(acc1[cp], yy, m2);
            }
        }
        __syncthreads();
    }

    float r0[OPT], r1[OPT];
    #pragma unroll
    for (int cp = 0; cp < OPT / 2; cp++) {
        upk(acc0[cp], r0[2 * cp], r0[2 * cp + 1]);
        upk(acc1[cp], r1[2 * cp], r1[2 * cp + 1]);
    }
    #pragma unroll
    for (int cc = 0; cc < OPT; cc++) {
        float bias = __ldg(&c[og * OPT + cc]);
        r0[cc] += bias;
        r1[cc] += bias;
    }
    const int nA = n0 + 2 * ng, nB = nA + 1;
    if (nA < N) {
        #pragma unroll
        for (int v = 0; v < OPT / 4; v++)
            *reinterpret_cast<float4*>(&out[(size_t)nA * KOUT + og * OPT + 4 * v]) =
                make_float4(r0[4 * v], r0[4 * v + 1], r0[4 * v + 2], r0[4 * v + 3]);
    }
    if (nB < N) {
        #pragma unroll
        for (int v = 0; v < OPT / 4; v++)
            *reinterpret_cast<float4*>(&out[(size_t)nB * KOUT + og * OPT + 4 * v]) =
                make_float4(r1[4 * v], r1[4 * v + 1], r1[4 * v + 2], r1[4 * v + 3]);
    }
}

__global__ void __launch_bounds__(256)
node_kernel(const float* __restrict__ xp, const float* __restrict__ xa,
            const float* __restrict__ Mp, const float* __restrict__ cp,
            const float* __restrict__ Ma, const float* __restrict__ ca,
            float* __restrict__ pL, float* __restrict__ aL,
            int Np, int Na, int npBlocks) {
    __shared__ float Xs[32 * 128];
    __shared__ float Ms[32 * 48];
    if ((int)blockIdx.x < npBlocks)
        node_body<256, 48, 12>(xp, Mp, cp, pL, Np, blockIdx.x, Xs, Ms);
    else
        node_body<128, 16, 4>(xa, Ma, ca, aL, Na, blockIdx.x - npBlocks, Xs, Ms);
}

// ---------------------------------------------------------------------------
// Kernel 3 (fused, merged edge types): quad-per-edge producer.
// Batch = 8 consecutive edges. Lane l: edge = l>>2, k-chunk = l&3.
//   GATHER: 2 coalesced idx LDG + 2 gather LDG.128 (float4 rows) per batch.
//   SOFTMAX: 4 exp/lane, in-lane sum, 2 width-4 shfls, rcp, 4 muls, STS.128.
//   Epilogue (per edge): 4 broadcast LDS.128 + reg {b,b} packs + 32 fma2
//                        + streaming STG.128.
// ---------------------------------------------------------------------------
__global__ void __launch_bounds__(256, 2)
edge_fused_kernel(const int* __restrict__ eiW, const int* __restrict__ eiC,
                  int E,
                  const float* __restrict__ aL, const float* __restrict__ pL,
                  const float* __restrict__ A_w, const float* __restrict__ A_c,
                  float* __restrict__ out, int nbHalf) {
    __shared__ __align__(16) float4 bsh[8][2][32];  // [warp][buf][edge*4 + kq]

    const bool isW = (int)blockIdx.x < nbHalf;
    const int bid = isW ? blockIdx.x : blockIdx.x - nbHalf;
    const int* ei = isW ? eiW : eiC;
    const float* srcL = isW ? aL : (pL + 16);
    const int sStride = isW ? 16 : 48;
    const float* dstL = isW ? pL : (pL + 32);
    const float* A = isW ? A_w : A_c;
    float* o = isW ? out : out + (size_t)E * 128;

    const int lane = threadIdx.x & 31;
    const int w = threadIdx.x >> 5;
    const int eSub = lane >> 2;   // edge within batch (0..7)
    const int kq = lane & 3;      // float4 chunk of the 16 logits

    // A preload: lane owns output columns [4*lane, 4*lane+4) for all 16 k.
    ull aLr[16], aHr[16];
    #pragma unroll
    for (int k = 0; k < 16; k++) {
        float4 v = reinterpret_cast<const float4*>(A)[k * 32 + lane];
        aLr[k] = pk2(v.x, v.y);
        aHr[k] = pk2(v.z, v.w);
    }

    const int gw = bid * 8 + w;
    const int base = gw * 8;               // first edge of this warp's batch 0
    const int step = nbHalf * 8 * 8;       // edges consumed per iter, all warps
    if (base >= E) return;
    const int nIter = (E - base + step - 1) / step;

    float4 lg;

    // gather + leaky-relu logits for batch t (clamped; safe for any t)
    #define GATHER(t_)                                                        \
        do {                                                                  \
            int e_ = min(base + (t_) * step + eSub, E - 1);                   \
            int s_ = __ldg(&ei[e_]);                                          \
            int d_ = __ldg(&ei[E + e_]);                                      \
            float4 ls_ = *reinterpret_cast<const float4*>(                    \
                &srcL[(size_t)s_ * sStride + 4 * kq]);                        \
            float4 ld_ = *reinterpret_cast<const float4*>(                    \
                &dstL[(size_t)d_ * 48 + 4 * kq]);                             \
            lg.x = ls_.x + ld_.x; lg.y = ls_.y + ld_.y;                       \
            lg.z = ls_.z + ld_.z; lg.w = ls_.w + ld_.w;                       \
            lg.x = fmaxf(lg.x, 0.01f * lg.x);                                 \
            lg.y = fmaxf(lg.y, 0.01f * lg.y);                                 \
            lg.z = fmaxf(lg.z, 0.01f * lg.z);                                 \
            lg.w = fmaxf(lg.w, 0.01f * lg.w);                                 \
        } while (0)

    // no-max softmax (logits bounded; fp32 headroom is huge) -> bsh[w][buf_]
    #define SOFTMAX_TO(buf_)                                                  \
        do {                                                                  \
            float4 ex_;                                                       \
            ex_.x = __expf(lg.x); ex_.y = __expf(lg.y);                       \
            ex_.z = __expf(lg.z); ex_.w = __expf(lg.w);                       \
            float s_ = (ex_.x + ex_.y) + (ex_.z + ex_.w);                     \
            s_ += __shfl_xor_sync(0xffffffffu, s_, 1, 4);                     \
            s_ += __shfl_xor_sync(0xffffffffu, s_, 2, 4);                     \
            float r_ = __fdividef(1.f, s_);                                   \
            ex_.x *= r_; ex_.y *= r_; ex_.z *= r_; ex_.w *= r_;               \
            bsh[w][buf_][lane] = ex_;                                         \
        } while (0)

    // prologue: batch 0 softmax into buf 0; issue batch-1 gathers
    GATHER(0);
    SOFTMAX_TO(0);
    GATHER(1);
    __syncwarp();

    for (int t = 0; t < nIter; t++) {
        const int buf = t & 1;

        // stage 1: softmax batch t+1 (gathers issued last iter) -> buf^1
        SOFTMAX_TO(buf ^ 1);
        // stage 2: issue gathers batch t+2 (fly under the FMA burst)
        GATHER(t + 2);

        // stage 3: epilogue batch t from bsh[buf]
        const int eb = base + t * step;
        #pragma unroll
        for (int v = 0; v < 8; v++) {
            if (eb + v < E) {
                const float4* brow = &bsh[w][buf][v * 4];
                ull accL = 0ull, accH = 0ull;
                #pragma unroll
                for (int q = 0; q < 4; q++) {
                    float4 bv = brow[q];     // broadcast LDS.128
                    ull b0 = pk2(bv.x, bv.x);
                    ull b1 = pk2(bv.y, bv.y);
                    ull b2 = pk2(bv.z, bv.z);
                    ull b3 = pk2(bv.w, bv.w);
                    fma2(accL, b0, aLr[4 * q + 0]);
                    fma2(accH, b0, aHr[4 * q + 0]);
                    fma2(accL, b1, aLr[4 * q + 1]);
                    fma2(accH, b1, aHr[4 * q + 1]);
                    fma2(accL, b2, aLr[4 * q + 2]);
                    fma2(accH, b2, aHr[4 * q + 2]);
                    fma2(accL, b3, aLr[4 * q + 3]);
                    fma2(accH, b3, aHr[4 * q + 3]);
                }
                st4cs(o + (size_t)(eb + v) * 128 + 4 * lane, accL, accH);
            }
        }
        __syncwarp();
    }
    #undef GATHER
    #undef SOFTMAX_TO
}

// ---------------------------------------------------------------------------
extern "C" void kernel_launch(void* const* d_in, const int* in_sizes, int n_in,
                              void* d_out, int out_size) {
    const float* x_paper   = (const float*)d_in[0];
    const float* x_author  = (const float*)d_in[1];
    const float* Wp_paper  = (const float*)d_in[2];
    const float* bp_paper  = (const float*)d_in[3];
    const float* Wp_author = (const float*)d_in[4];
    const float* bp_author = (const float*)d_in[5];
    const float* Ws_writes = (const float*)d_in[6];
    const float* bs_writes = (const float*)d_in[7];
    const float* A_writes  = (const float*)d_in[8];
    const float* Ws_cites  = (const float*)d_in[9];
    const float* bs_cites  = (const float*)d_in[10];
    const float* A_cites   = (const float*)d_in[11];
    const int*   ei_writes = (const int*)d_in[12];
    const int*   ei_cites  = (const int*)d_in[13];
    float* out = (float*)d_out;

    const int Np = in_sizes[0] / 256;
    const int Na = in_sizes[1] / 128;
    const int E  = in_sizes[12] / 2;

    float *fold, *pL, *aL;
    cudaGetSymbolAddress((void**)&fold, g_fold);
    cudaGetSymbolAddress((void**)&pL, g_paperL);
    cudaGetSymbolAddress((void**)&aL, g_authorL);
    float* Mp = fold;
    float* Ma = fold + 12288;
    float* cp = fold + 14336;
    float* ca = fold + 14384;

    cudaMemsetAsync(fold, 0, 14400 * sizeof(float));

    fold_kernel<<<dim3(64, 4), 256>>>(Wp_paper, bp_paper, Wp_author, bp_author,
                                      Ws_writes, bs_writes, Ws_cites, bs_cites);

    const int npB = (Np + 127) / 128;
    const int naB = (Na + 127) / 128;
    node_kernel<<<npB + naB, 256>>>(x_paper, x_author, Mp, cp, Ma, ca,
                                    pL, aL, Np, Na, npB);

    const int nbHalf = 148;  // persistent single wave: 2 CTAs/SM
    edge_fused_kernel<<<2 * nbHalf, 256>>>(ei_writes, ei_cites, E, aL, pL,
                                           A_writes, A_cites, out, nbHalf);
}

// round 14
// speedup vs baseline: 1.3129x; 1.1307x over previous
#include <cuda_runtime.h>
#include <cuda_bf16.h>
#include <cstdint>

// ---------------------------------------------------------------------------
// HeteroEdgePromptPlus — folded formulation.
//   logits[e,k] = srcLogits[src(e),k] + dstLogits[dst(e),k]   (bias folded)
//   b = softmax(leaky_relu(logits)) ; out[e] = b @ A
// Fused edge kernel: 3-stage SW pipeline at 16-edge granularity; quad-per-edge
// float4 gathers, width-4 softmax, unduplicated b in smem, A-in-regs consumer
// with broadcast LDS + streaming STG.128 (immediate-offset, hoisted bounds).
// ---------------------------------------------------------------------------

#define MAXN 50000
typedef unsigned long long ull;

// fold outputs in ONE buffer (single memset): Mp | Ma | cp | ca
__device__ float g_fold[48 * 256 + 16 * 128 + 48 + 16];
#define G_MP (g_fold)
#define G_MA (g_fold + 12288)
#define G_CP (g_fold + 14336)
#define G_CA (g_fold + 14384)
__device__ float g_paperL[(size_t)MAXN * 48];
__device__ float g_authorL[(size_t)MAXN * 16];

// ---- f32x2 packed helpers (Blackwell) -------------------------------------
__device__ __forceinline__ ull pk2(float x, float y) {
    ull r;
    asm("mov.b64 %0, {%1, %2};" : "=l"(r) : "f"(x), "f"(y));
    return r;
}
__device__ __forceinline__ void upk(ull v, float& x, float& y) {
    asm("mov.b64 {%0, %1}, %2;" : "=f"(x), "=f"(y) : "l"(v));
}
__device__ __forceinline__ void fma2(ull& d, ull a, ull b) {
    asm("fma.rn.f32x2 %0, %1, %2, %0;" : "+l"(d) : "l"(a), "l"(b));
}
__device__ __forceinline__ void st4cs(float* p, ull a, ull b) {
    float x, y, z, w;
    upk(a, x, y);
    upk(b, z, w);
    asm volatile("st.global.cs.v4.f32 [%0], {%1, %2, %3, %4};"
                 :: "l"(p), "f"(x), "f"(y), "f"(z), "f"(w) : "memory");
}

// ---------------------------------------------------------------------------
// Kernel 1: fold weights. grid = (64, 4): x = output row, y = p-chunk of 32.
// ---------------------------------------------------------------------------
__global__ void fold_kernel(const float* __restrict__ Wp_p,
                            const float* __restrict__ bp_p,
                            const float* __restrict__ Wp_a,
                            const float* __restrict__ bp_a,
                            const float* __restrict__ Ws_w,
                            const float* __restrict__ bs_w,
                            const float* __restrict__ Ws_c,
                            const float* __restrict__ bs_c) {
    const int b = blockIdx.x, t = threadIdx.x;
    const int pBeg = blockIdx.y * 32, pEnd = pBeg + 32;
    if (b < 48) {
        int k = b & 15, grp = b >> 4;
        const float* wrow = (grp == 0) ? (Ws_w + k * 256 + 128)
                          : (grp == 1) ? (Ws_c + k * 256)
                                       : (Ws_c + k * 256 + 128);
        float a0 = 0.f, a1 = 0.f, a2 = 0.f, a3 = 0.f;
        #pragma unroll
        for (int p = pBeg; p < pEnd; p += 4) {
            a0 = fmaf(__ldg(&wrow[p + 0]), __ldg(&Wp_p[(p + 0) * 256 + t]), a0);
            a1 = fmaf(__ldg(&wrow[p + 1]), __ldg(&Wp_p[(p + 1) * 256 + t]), a1);
            a2 = fmaf(__ldg(&wrow[p + 2]), __ldg(&Wp_p[(p + 2) * 256 + t]), a2);
            a3 = fmaf(__ldg(&wrow[p + 3]), __ldg(&Wp_p[(p + 3) * 256 + t]), a3);
        }
        atomicAdd(&G_MP[b * 256 + t], (a0 + a1) + (a2 + a3));
        if (t == 0) {
            float c0 = (blockIdx.y == 0)
                           ? ((grp == 0) ? bs_w[k] : (grp == 2) ? bs_c[k] : 0.f)
                           : 0.f;
            float c1 = 0.f, c2 = 0.f, c3 = 0.f;
            #pragma unroll
            for (int p = pBeg; p < pEnd; p += 4) {
                c0 = fmaf(wrow[p + 0], bp_p[p + 0], c0);
                c1 = fmaf(wrow[p + 1], bp_p[p + 1], c1);
                c2 = fmaf(wrow[p + 2], bp_p[p + 2], c2);
                c3 = fmaf(wrow[p + 3], bp_p[p + 3], c3);
            }
            atomicAdd(&G_CP[b], (c0 + c1) + (c2 + c3));
        }
    } else {
        int k = b - 48;
        if (t < 128) {
            const float* wrow = Ws_w + k * 256;  // src half -> author
            float a0 = 0.f, a1 = 0.f, a2 = 0.f, a3 = 0.f;
            #pragma unroll
            for (int p = pBeg; p < pEnd; p += 4) {
                a0 = fmaf(__ldg(&wrow[p + 0]), __ldg(&Wp_a[(p + 0) * 128 + t]), a0);
                a1 = fmaf(__ldg(&wrow[p + 1]), __ldg(&Wp_a[(p + 1) * 128 + t]), a1);
                a2 = fmaf(__ldg(&wrow[p + 2]), __ldg(&Wp_a[(p + 2) * 128 + t]), a2);
                a3 = fmaf(__ldg(&wrow[p + 3]), __ldg(&Wp_a[(p + 3) * 128 + t]), a3);
            }
            atomicAdd(&G_MA[k * 128 + t], (a0 + a1) + (a2 + a3));
            if (t == 0) {
                float c0 = 0.f, c1 = 0.f, c2 = 0.f, c3 = 0.f;
                #pragma unroll
                for (int p = pBeg; p < pEnd; p += 4) {
                    c0 = fmaf(wrow[p + 0], bp_a[p + 0], c0);
                    c1 = fmaf(wrow[p + 1], bp_a[p + 1], c1);
                    c2 = fmaf(wrow[p + 2], bp_a[p + 2], c2);
                    c3 = fmaf(wrow[p + 3], bp_a[p + 3], c3);
                }
                atomicAdd(&G_CA[k], (c0 + c1) + (c2 + c3));
            }
        }
    }
}

// ---------------------------------------------------------------------------
// Kernel 2: node logits  out[N,KOUT] = X[N,KDIM] @ M[KOUT,KDIM].T + c
// ---------------------------------------------------------------------------
template <int KDIM, int KOUT, int OPT>
__device__ __forceinline__ void node_body(const float* __restrict__ X,
                                          const float* __restrict__ M,
                                          const float* __restrict__ c,
                                          float* __restrict__ out, int N,
                                          int blk, float* Xs, float* Ms) {
    constexpr int KT = 32;
    const int t = threadIdx.x;
    const int n0 = blk * 128;
    const int ng = t & 63;
    const int og = t >> 6;

    ull acc0[OPT / 2], acc1[OPT / 2];
    #pragma unroll
    for (int i = 0; i < OPT / 2; i++) { acc0[i] = 0ull; acc1[i] = 0ull; }

    const int sn = n0 + (t >> 1);
    const int sj = (t & 1) * 16;
    const bool vs = sn < N;
    const float* xrow = X + (size_t)(vs ? sn : (N - 1)) * KDIM;

    for (int j0 = 0; j0 < KDIM; j0 += KT) {
        #pragma unroll
        for (int q = 0; q < 4; q++) {
            float4 v = vs ? *reinterpret_cast<const float4*>(xrow + j0 + sj + 4 * q)
                          : make_float4(0.f, 0.f, 0.f, 0.f);
            int jj = sj + 4 * q;
            Xs[(jj + 0) * 128 + (t >> 1)] = v.x;
            Xs[(jj + 1) * 128 + (t >> 1)] = v.y;
            Xs[(jj + 2) * 128 + (t >> 1)] = v.z;
            Xs[(jj + 3) * 128 + (t >> 1)] = v.w;
        }
        #pragma unroll
        for (int idx = t; idx < KT * KOUT; idx += 256) {
            int j = idx / KOUT, k = idx - j * KOUT;
            Ms[j * KOUT + k] = M[k * KDIM + j0 + j];
        }
        __syncthreads();
        #pragma unroll
        for (int j = 0; j < KT; j++) {
            float2 xv = *reinterpret_cast<const float2*>(&Xs[j * 128 + 2 * ng]);
            ull xx = pk2(xv.x, xv.x);
            ull yy = pk2(xv.y, xv.y);
            #pragma unroll
            for (int cp = 0; cp < OPT / 2; cp++) {
                ull m2 = *reinterpret_cast<const ull*>(&Ms[j * KOUT + og * OPT + 2 * cp]);
                fma2(acc0[cp], xx, m2);
                fma2(acc1[cp], yy, m2);
            }
        }
        __syncthreads();
    }

    float r0[OPT], r1[OPT];
    #pragma unroll
    for (int cp = 0; cp < OPT / 2; cp++) {
        upk(acc0[cp], r0[2 * cp], r0[2 * cp + 1]);
        upk(acc1[cp], r1[2 * cp], r1[2 * cp + 1]);
    }
    #pragma unroll
    for (int cc = 0; cc < OPT; cc++) {
        float bias = __ldg(&c[og * OPT + cc]);
        r0[cc] += bias;
        r1[cc] += bias;
    }
    const int nA = n0 + 2 * ng, nB = nA + 1;
    if (nA < N) {
        #pragma unroll
        for (int v = 0; v < OPT / 4; v++)
            *reinterpret_cast<float4*>(&out[(size_t)nA * KOUT + og * OPT + 4 * v]) =
                make_float4(r0[4 * v], r0[4 * v + 1], r0[4 * v + 2], r0[4 * v + 3]);
    }
    if (nB < N) {
        #pragma unroll
        for (int v = 0; v < OPT / 4; v++)
            *reinterpret_cast<float4*>(&out[(size_t)nB * KOUT + og * OPT + 4 * v]) =
                make_float4(r1[4 * v], r1[4 * v + 1], r1[4 * v + 2], r1[4 * v + 3]);
    }
}

__global__ void __launch_bounds__(256)
node_kernel(const float* __restrict__ xp, const float* __restrict__ xa,
            const float* __restrict__ Mp, const float* __restrict__ cp,
            const float* __restrict__ Ma, const float* __restrict__ ca,
            float* __restrict__ pL, float* __restrict__ aL,
            int Np, int Na, int npBlocks) {
    __shared__ float Xs[32 * 128];
    __shared__ float Ms[32 * 48];
    if ((int)blockIdx.x < npBlocks)
        node_body<256, 48, 12>(xp, Mp, cp, pL, Np, blockIdx.x, Xs, Ms);
    else
        node_body<128, 16, 4>(xa, Ma, ca, aL, Na, blockIdx.x - npBlocks, Xs, Ms);
}

// ---------------------------------------------------------------------------
// Kernel 3 (fused, merged edge types): 16 edges per pipeline stage.
// Lane l: edge = l>>2 (+8 for sub-batch B), k-chunk = l&3.
//   GATHER: 4 idx LDG + 4 gather LDG.128 per lane-pair of sub-batches.
//   SOFTMAX: 2 interleaved width-4 chains, 2 STS.128.
//   Epilogue: fast path = 16 x (4 broadcast LDS.128 + 16 pk2 + 32 fma2 +
//             immediate-offset streaming STG.128), no per-edge predicates.
// ---------------------------------------------------------------------------
__global__ void __launch_bounds__(256, 2)
edge_fused_kernel(const int* __restrict__ eiW, const int* __restrict__ eiC,
                  int E,
                  const float* __restrict__ aL, const float* __restrict__ pL,
                  const float* __restrict__ A_w, const float* __restrict__ A_c,
                  float* __restrict__ out, int nbHalf) {
    __shared__ __align__(16) float4 bsh[8][2][2][32]; // [warp][buf][sub][e*4+kq]

    const bool isW = (int)blockIdx.x < nbHalf;
    const int bid = isW ? blockIdx.x : blockIdx.x - nbHalf;
    const int* ei = isW ? eiW : eiC;
    const float* srcL = isW ? aL : (pL + 16);
    const int sStride = isW ? 16 : 48;
    const float* dstL = isW ? pL : (pL + 32);
    const float* A = isW ? A_w : A_c;
    float* o = isW ? out : out + (size_t)E * 128;

    const int lane = threadIdx.x & 31;
    const int w = threadIdx.x >> 5;
    const int eSub = lane >> 2;   // edge within sub-batch (0..7)
    const int kq = lane & 3;      // float4 chunk of the 16 logits

    // A preload: lane owns output columns [4*lane, 4*lane+4) for all 16 k.
    ull aLr[16], aHr[16];
    #pragma unroll
    for (int k = 0; k < 16; k++) {
        float4 v = reinterpret_cast<const float4*>(A)[k * 32 + lane];
        aLr[k] = pk2(v.x, v.y);
        aHr[k] = pk2(v.z, v.w);
    }

    const int gw = bid * 8 + w;
    const int base = gw * 16;               // first edge of this warp's batch 0
    const int step = nbHalf * 8 * 16;       // edges consumed per iter, all warps
    if (base >= E) return;
    const int nIter = (E - base + step - 1) / step;

    float4 lgA, lgB;

    // gather + leaky-relu logits for 16-edge batch t (clamped; safe any t)
    #define GATHER(t_)                                                        \
        do {                                                                  \
            int eA_ = min(base + (t_) * step + eSub, E - 1);                  \
            int eB_ = min(base + (t_) * step + eSub + 8, E - 1);              \
            int sA_ = __ldg(&ei[eA_]);                                        \
            int dA_ = __ldg(&ei[E + eA_]);                                    \
            int sB_ = __ldg(&ei[eB_]);                                        \
            int dB_ = __ldg(&ei[E + eB_]);                                    \
            float4 lsA_ = *reinterpret_cast<const float4*>(                   \
                &srcL[(size_t)sA_ * sStride + 4 * kq]);                       \
            float4 ldA_ = *reinterpret_cast<const float4*>(                   \
                &dstL[(size_t)dA_ * 48 + 4 * kq]);                            \
            float4 lsB_ = *reinterpret_cast<const float4*>(                   \
                &srcL[(size_t)sB_ * sStride + 4 * kq]);                       \
            float4 ldB_ = *reinterpret_cast<const float4*>(                   \
                &dstL[(size_t)dB_ * 48 + 4 * kq]);                            \
            lgA.x = lsA_.x + ldA_.x; lgA.y = lsA_.y + ldA_.y;                 \
            lgA.z = lsA_.z + ldA_.z; lgA.w = lsA_.w + ldA_.w;                 \
            lgB.x = lsB_.x + ldB_.x; lgB.y = lsB_.y + ldB_.y;                 \
            lgB.z = lsB_.z + ldB_.z; lgB.w = lsB_.w + ldB_.w;                 \
            lgA.x = fmaxf(lgA.x, 0.01f * lgA.x);                              \
            lgA.y = fmaxf(lgA.y, 0.01f * lgA.y);                              \
            lgA.z = fmaxf(lgA.z, 0.01f * lgA.z);                              \
            lgA.w = fmaxf(lgA.w, 0.01f * lgA.w);                              \
            lgB.x = fmaxf(lgB.x, 0.01f * lgB.x);                              \
            lgB.y = fmaxf(lgB.y, 0.01f * lgB.y);                              \
            lgB.z = fmaxf(lgB.z, 0.01f * lgB.z);                              \
            lgB.w = fmaxf(lgB.w, 0.01f * lgB.w);                              \
        } while (0)

    // no-max softmax (logits bounded; fp32 headroom huge), 2 chains -> bsh
    #define SOFTMAX_TO(buf_)                                                  \
        do {                                                                  \
            float4 exA_, exB_;                                                \
            exA_.x = __expf(lgA.x); exA_.y = __expf(lgA.y);                   \
            exA_.z = __expf(lgA.z); exA_.w = __expf(lgA.w);                   \
            exB_.x = __expf(lgB.x); exB_.y = __expf(lgB.y);                   \
            exB_.z = __expf(lgB.z); exB_.w = __expf(lgB.w);                   \
            float sA_ = (exA_.x + exA_.y) + (exA_.z + exA_.w);                \
            float sB_ = (exB_.x + exB_.y) + (exB_.z + exB_.w);                \
            sA_ += __shfl_xor_sync(0xffffffffu, sA_, 1, 4);                   \
            sB_ += __shfl_xor_sync(0xffffffffu, sB_, 1, 4);                   \
            sA_ += __shfl_xor_sync(0xffffffffu, sA_, 2, 4);                   \
            sB_ += __shfl_xor_sync(0xffffffffu, sB_, 2, 4);                   \
            float rA_ = __fdividef(1.f, sA_);                                 \
            float rB_ = __fdividef(1.f, sB_);                                 \
            exA_.x *= rA_; exA_.y *= rA_; exA_.z *= rA_; exA_.w *= rA_;       \
            exB_.x *= rB_; exB_.y *= rB_; exB_.z *= rB_; exB_.w *= rB_;       \
            bsh[w][buf_][0][lane] = exA_;                                     \
            bsh[w][buf_][1][lane] = exB_;                                     \
        } while (0)

    // one edge of epilogue from brow (4 broadcast LDS.128 + 32 fma2)
    #define EDGE_MM(brow_, dst_)                                              \
        do {                                                                  \
            ull accL_ = 0ull, accH_ = 0ull;                                   \
            _Pragma("unroll")                                                 \
            for (int q = 0; q < 4; q++) {                                     \
                float4 bv_ = (brow_)[q];                                      \
                ull b0_ = pk2(bv_.x, bv_.x);                                  \
                ull b1_ = pk2(bv_.y, bv_.y);                                  \
                ull b2_ = pk2(bv_.z, bv_.z);                                  \
                ull b3_ = pk2(bv_.w, bv_.w);                                  \
                fma2(accL_, b0_, aLr[4 * q + 0]);                             \
                fma2(accH_, b0_, aHr[4 * q + 0]);                             \
                fma2(accL_, b1_, aLr[4 * q + 1]);                             \
                fma2(accH_, b1_, aHr[4 * q + 1]);                             \
                fma2(accL_, b2_, aLr[4 * q + 2]);                             \
                fma2(accH_, b2_, aHr[4 * q + 2]);                             \
                fma2(accL_, b3_, aLr[4 * q + 3]);                             \
                fma2(accH_, b3_, aHr[4 * q + 3]);                             \
            }                                                                 \
            st4cs(dst_, accL_, accH_);                                        \
        } while (0)

    // prologue: batch 0 softmax into buf 0; issue batch-1 gathers
    GATHER(0);
    SOFTMAX_TO(0);
    GATHER(1);
    __syncwarp();

    for (int t = 0; t < nIter; t++) {
        const int buf = t & 1;

        // stage 1: softmax batch t+1 (gathers issued last iter) -> buf^1
        SOFTMAX_TO(buf ^ 1);
        // stage 2: issue gathers batch t+2 (fly under the FMA burst)
        GATHER(t + 2);

        // stage 3: epilogue batch t from bsh[buf]
        const int eb = base + t * step;
        float* obase = o + (size_t)eb * 128 + 4 * lane;
        if (eb + 16 <= E) {
            // fast path: no per-edge predicates, immediate-offset stores
            #pragma unroll
            for (int v = 0; v < 16; v++) {
                const float4* brow = &bsh[w][buf][v >> 3][(v & 7) * 4];
                EDGE_MM(brow, obase + (size_t)v * 128);
            }
        } else {
            #pragma unroll
            for (int v = 0; v < 16; v++) {
                if (eb + v < E) {
                    const float4* brow = &bsh[w][buf][v >> 3][(v & 7) * 4];
                    EDGE_MM(brow, obase + (size_t)v * 128);
                }
            }
        }
        __syncwarp();
    }
    #undef GATHER
    #undef SOFTMAX_TO
    #undef EDGE_MM
}

// ---------------------------------------------------------------------------
extern "C" void kernel_launch(void* const* d_in, const int* in_sizes, int n_in,
                              void* d_out, int out_size) {
    const float* x_paper   = (const float*)d_in[0];
    const float* x_author  = (const float*)d_in[1];
    const float* Wp_paper  = (const float*)d_in[2];
    const float* bp_paper  = (const float*)d_in[3];
    const float* Wp_author = (const float*)d_in[4];
    const float* bp_author = (const float*)d_in[5];
    const float* Ws_writes = (const float*)d_in[6];
    const float* bs_writes = (const float*)d_in[7];
    const float* A_writes  = (const float*)d_in[8];
    const float* Ws_cites  = (const float*)d_in[9];
    const float* bs_cites  = (const float*)d_in[10];
    const float* A_cites   = (const float*)d_in[11];
    const int*   ei_writes = (const int*)d_in[12];
    const int*   ei_cites  = (const int*)d_in[13];
    float* out = (float*)d_out;

    const int Np = in_sizes[0] / 256;
    const int Na = in_sizes[1] / 128;
    const int E  = in_sizes[12] / 2;

    float *fold, *pL, *aL;
    cudaGetSymbolAddress((void**)&fold, g_fold);
    cudaGetSymbolAddress((void**)&pL, g_paperL);
    cudaGetSymbolAddress((void**)&aL, g_authorL);
    float* Mp = fold;
    float* Ma = fold + 12288;
    float* cp = fold + 14336;
    float* ca = fold + 14384;

    cudaMemsetAsync(fold, 0, 14400 * sizeof(float));

    fold_kernel<<<dim3(64, 4), 256>>>(Wp_paper, bp_paper, Wp_author, bp_author,
                                      Ws_writes, bs_writes, Ws_cites, bs_cites);

    const int npB = (Np + 127) / 128;
    const int naB = (Na + 127) / 128;
    node_kernel<<<npB + naB, 256>>>(x_paper, x_author, Mp, cp, Ma, ca,
                                    pL, aL, Np, Na, npB);

    const int nbHalf = 148;  // persistent single wave: 2 CTAs/SM
    edge_fused_kernel<<<2 * nbHalf, 256>>>(ei_writes, ei_cites, E, aL, pL,
                                           A_writes, A_cites, out, nbHalf);
}